// round 9
// baseline (speedup 1.0000x reference)
#include <cuda_runtime.h>
#include <math.h>

#define NQ       22
#define NSTATES  (1u << NQ)
#define NPAIRS   (1u << (NQ - 1))

// Sanctioned scratch (no allocation). All intermediates live here; d_out is
// written exactly once, strictly bounded by out_size.
__device__ float2 g_state[NSTATES];
__device__ float2 g_tmp[NSTATES];

// CNOT chain q -> q+1 (q=0..20): |x> -> |y>, y_k = x_0 ^ ... ^ x_k
// (inclusive prefix parity). Bijection on [0, 2^22).
__device__ __forceinline__ unsigned pxor22(unsigned x) {
    x ^= x << 1;  x ^= x << 2;  x ^= x << 4;  x ^= x << 8;  x ^= x << 16;
    return x & (NSTATES - 1u);
}

// Pack planar real/imag inputs into interleaved float2 scratch.
__global__ void __launch_bounds__(256)
pack_state(const float* __restrict__ re, const float* __restrict__ im) {
    const unsigned i = blockIdx.x * 256u + threadIdx.x;
    if (i >= NSTATES) return;
    g_state[i] = make_float2(re[i], im[i]);
}

// One RY butterfly on qubit q, in place over disjoint index pairs.
// buf: 0 = g_state, 1 = g_tmp.  pidx < 66.
// RY: new0 = c*a0 - s*a1 ; new1 = s*a0 + c*a1 (real gate; identical coeffs
// applied to the real (.x) and imaginary (.y) components).
__global__ void __launch_bounds__(256)
ry_gate(int buf, const float* __restrict__ params, int pidx, int q) {
    float2* b = buf ? g_tmp : g_state;
    const unsigned tid = blockIdx.x * 256u + threadIdx.x;
    if (tid >= NPAIRS) return;
    float s, c;
    sincosf(0.5f * __ldg(&params[pidx]), &s, &c);
    const unsigned low = tid & ((1u << q) - 1u);
    const unsigned i0  = ((tid >> q) << (q + 1)) | low;   // bit q = 0
    const unsigned i1  = i0 | (1u << q);                  // bit q = 1
    const float2 a0 = b[i0];
    const float2 a1 = b[i1];
    b[i0] = make_float2(c * a0.x - s * a1.x, c * a0.y - s * a1.y);
    b[i1] = make_float2(s * a0.x + c * a1.x, s * a0.y + c * a1.y);
}

// CNOT-chain permutation between the two scratch buffers.
// dir=0: g_state -> g_tmp ; dir=1: g_tmp -> g_state.
__global__ void __launch_bounds__(256)
perm_chain(int dir) {
    const unsigned g = blockIdx.x * 256u + threadIdx.x;
    if (g >= NSTATES) return;
    if (dir == 0) g_tmp[pxor22(g)]   = g_state[g];
    else          g_state[pxor22(g)] = g_tmp[g];
}

// Final store, PLANAR layout: out[0 .. N) = real parts, out[N .. 2N) = imag
// parts. Strictly bounded by n_floats (<= min(out_size, 2*NSTATES)).
__global__ void __launch_bounds__(256)
store_out_planar(float* __restrict__ out, long long n_floats) {
    const long long i = (long long)blockIdx.x * 256 + threadIdx.x;
    if (i >= n_floats) return;
    if (i < (long long)NSTATES) out[i] = g_state[(unsigned)i].x;
    else                        out[i] = g_state[(unsigned)(i - NSTATES)].y;
}

extern "C" void kernel_launch(void* const* d_in, const int* in_sizes, int n_in,
                              void* d_out, int out_size) {
    if (n_in < 3) return;
    // Binding: params = smallest input; the remaining two, in original order,
    // are state_real, state_imag. Never index past n_in.
    int pi = 0;
    for (int i = 1; i < n_in && i < 8; i++)
        if (in_sizes[i] < in_sizes[pi]) pi = i;
    int si0 = -1, si1 = -1;
    for (int i = 0; i < n_in && i < 8; i++) {
        if (i == pi) continue;
        if (si0 < 0) si0 = i; else if (si1 < 0) si1 = i;
    }
    if (si0 < 0 || si1 < 0) return;
    if ((unsigned)in_sizes[si0] < NSTATES || (unsigned)in_sizes[si1] < NSTATES)
        return;   // clean validation failure instead of UB

    const float* params = (const float*)d_in[pi];
    const float* sre    = (const float*)d_in[si0];
    const float* sim    = (const float*)d_in[si1];
    float*       out    = (float*)d_out;

    // Output write bound: at most out_size float components, capped at the
    // full result size (2^23 floats = 32 MB). Proven safe in round 7.
    long long n_floats = (long long)out_size;
    if (n_floats > 2LL * NSTATES) n_floats = 2LL * NSTATES;
    if (n_floats <= 0) return;

    const unsigned GB_FULL = NSTATES / 256u;                        // 16384
    const unsigned GB_HALF = NPAIRS  / 256u;                        //  8192
    const unsigned GB_OUT  = (unsigned)((n_floats + 255) / 256);

    pack_state<<<GB_FULL, 256>>>(sre, sim);

    // Layer 0 (in g_state), then CNOT chain -> g_tmp.
    for (int q = 0; q < NQ; q++)
        ry_gate<<<GB_HALF, 256>>>(0, params, q, q);
    perm_chain<<<GB_FULL, 256>>>(0);
    // Layer 1 (in g_tmp), then CNOT chain -> g_state.
    for (int q = 0; q < NQ; q++)
        ry_gate<<<GB_HALF, 256>>>(1, params, NQ + q, q);
    perm_chain<<<GB_FULL, 256>>>(1);
    // Layer 2 (in g_state); no chain after the last layer.
    for (int q = 0; q < NQ; q++)
        ry_gate<<<GB_HALF, 256>>>(0, params, 2 * NQ + q, q);

    store_out_planar<<<GB_OUT, 256>>>(out, n_floats);
}

// round 12
// speedup vs baseline: 4.9110x; 4.9110x over previous
#include <cuda_runtime.h>
#include <math.h>

#define NQ       22
#define NSTATES  (1u << NQ)
#define MASK22   (NSTATES - 1u)

// Ping-pong scratch (sanctioned __device__ globals; no allocation).
__device__ float2 g_A[NSTATES];
__device__ float2 g_B[NSTATES];

// Inverse of the CNOT-chain permutation pxor (y_k = x_0^..^x_k):
// x = pinv(y), x_k = y_k ^ y_{k-1}  ->  pinv(y) = (y ^ (y<<1)) & mask.
// Used as a GATHER on the pass after a layer boundary:
//   w[y] = u[pinv(y)]  <=>  w[pxor(x)] = u[x].
__device__ __forceinline__ unsigned pinv22(unsigned y) {
    return (y ^ (y << 1)) & MASK22;
}

// Bank-conflict-avoiding smem swizzle: XOR bits [7:4] into [3:0].
// Conflict-free per half-warp for all three ownership patterns below.
__device__ __forceinline__ unsigned sw(unsigned v) {
    return v ^ ((v >> 4) & 15u);
}

// Up to 4 RY butterfly stages on 16 register-resident amplitudes.
// Register-index bit s <-> stage s; MASK selects active stages.
// RY: new0 = c*a0 - s*a1 ; new1 = s*a0 + c*a1 (same coeffs for re & im).
template<int MASK>
__device__ __forceinline__ void group4(float2 (&r)[16],
                                       const float* __restrict__ CB,
                                       const float* __restrict__ SB) {
#pragma unroll
    for (int s = 0; s < 4; s++) {
        if (((MASK >> s) & 1) == 0) continue;
        const float c  = CB[s];
        const float sn = SB[s];
#pragma unroll
        for (int p = 0; p < 8; p++) {
            const int m  = ((p >> s) << (s + 1)) | (p & ((1 << s) - 1));
            const int m1 = m | (1 << s);
            const float2 a0 = r[m], a1 = r[m1];
            r[m]  = make_float2(c  * a0.x - sn * a1.x, c  * a0.y - sn * a1.y);
            r[m1] = make_float2(sn * a0.x + c  * a1.x, sn * a0.y + c  * a1.y);
        }
    }
}

// One full-state pass: 1024 blocks x 256 threads, 4096 amps/block, 16/thread.
// Local index v (12 bits):
//   LOW:  g = blk<<12 | v                  (v bits 0..11 = qubits 0..11,
//          params pbase+0..11)
//   HIGH: g = (v>>2)<<12 | blk<<2 | (v&3)  (v bits 2..11 = qubits 12..21,
//          params pbase+0..9; v bits 0..1 ride along, identity)
// GATHER: load src[pinv22(g)] (folds the preceding CNOT-chain permutation).
// IN_PLANAR: load from planar sre/sim. OUT_REAL: store ONLY real parts to
// outp[g] (harness output = float32 real components; proven round 9/11).
// write_imag: if nonzero, also store outp[g + NSTATES] = imag (only when the
// harness buffer is known to hold 2*NSTATES floats).
template<bool HIGH, bool GATHER, bool IN_PLANAR, bool OUT_REAL>
__global__ void __launch_bounds__(256)
vqc_fused(const float* __restrict__ sre, const float* __restrict__ sim,
          float* __restrict__ outp, int write_imag, int srcsel, int dstsel,
          const float* __restrict__ params, int pbase)
{
    __shared__ float2 S[4096];
    __shared__ float CB[12];
    __shared__ float SB[12];

    const float2* __restrict__ src = (srcsel == 1) ? g_A : g_B;
    float2* __restrict__ dst       = (dstsel == 1) ? g_A : g_B;

    const unsigned t   = threadIdx.x;
    const unsigned blk = blockIdx.x;

    // Rotation coefficients per v-bit. HIGH: v bits 0,1 are identity.
    if (t < 12) {
        float c = 1.f, s = 0.f;
        if (!HIGH || t >= 2) {
            const float a = params[pbase + (HIGH ? (int)t - 2 : (int)t)];
            sincosf(0.5f * a, &s, &c);
        }
        CB[t] = c; SB[t] = s;
    }

    // ---- Global load, pattern A: v = (i<<8) | t ----
#pragma unroll
    for (int i = 0; i < 16; i++) {
        const unsigned v = ((unsigned)i << 8) | t;
        const unsigned g = HIGH
            ? (((((unsigned)i << 6) | (t >> 2)) << 12) | (blk << 2) | (t & 3u))
            : ((blk << 12) | v);
        float2 val;
        if (IN_PLANAR) {
            val = make_float2(sre[g], sim[g]);
        } else {
            const unsigned idx = GATHER ? pinv22(g) : g;
            val = src[idx];
        }
        S[sw(v)] = val;
    }
    __syncthreads();   // tile + coefficients ready

    float2 r[16];

    // ---- Pattern C (reg index = v bits 0..3): stages 0..3 ----
#pragma unroll
    for (int i = 0; i < 16; i++) { const unsigned v = (t << 4) | (unsigned)i; r[i] = S[sw(v)]; }
    if (HIGH) group4<0xC>(r, CB, SB);   // bits 0,1 identity
    else      group4<0xF>(r, CB, SB);
#pragma unroll
    for (int i = 0; i < 16; i++) { const unsigned v = (t << 4) | (unsigned)i; S[sw(v)] = r[i]; }
    __syncthreads();

    // ---- Pattern B (reg index = v bits 4..7): stages 4..7 ----
#pragma unroll
    for (int i = 0; i < 16; i++) {
        const unsigned v = ((t >> 4) << 8) | ((unsigned)i << 4) | (t & 15u);
        r[i] = S[sw(v)];
    }
    group4<0xF>(r, CB + 4, SB + 4);
#pragma unroll
    for (int i = 0; i < 16; i++) {
        const unsigned v = ((t >> 4) << 8) | ((unsigned)i << 4) | (t & 15u);
        S[sw(v)] = r[i];
    }
    __syncthreads();

    // ---- Pattern A (reg index = v bits 8..11): stages 8..11, then store ----
#pragma unroll
    for (int i = 0; i < 16; i++) { const unsigned v = ((unsigned)i << 8) | t; r[i] = S[sw(v)]; }
    group4<0xF>(r, CB + 8, SB + 8);

#pragma unroll
    for (int i = 0; i < 16; i++) {
        const unsigned v = ((unsigned)i << 8) | t;
        const unsigned g = HIGH
            ? (((((unsigned)i << 6) | (t >> 2)) << 12) | (blk << 2) | (t & 3u))
            : ((blk << 12) | v);
        if (OUT_REAL) {
            outp[g] = r[i].x;                              // real plane (16 MB)
            if (write_imag) outp[g + NSTATES] = r[i].y;    // only if buffer holds it
        } else {
            dst[g] = r[i];
        }
    }
}

extern "C" void kernel_launch(void* const* d_in, const int* in_sizes, int n_in,
                              void* d_out, int out_size) {
    if (n_in < 3) return;
    // Binding (proven round 9): params = smallest input; remaining two in
    // original order are state_real, state_imag. Never index past n_in.
    int pi = 0;
    for (int i = 1; i < n_in && i < 8; i++)
        if (in_sizes[i] < in_sizes[pi]) pi = i;
    int si0 = -1, si1 = -1;
    for (int i = 0; i < n_in && i < 8; i++) {
        if (i == pi) continue;
        if (si0 < 0) si0 = i; else if (si1 < 0) si1 = i;
    }
    if (si0 < 0 || si1 < 0) return;
    if ((unsigned)in_sizes[si0] < NSTATES || (unsigned)in_sizes[si1] < NSTATES)
        return;
    // Output contract (proven rounds 9+11): out_size = NSTATES float32
    // components = the REAL parts of the final state.
    if ((unsigned)out_size < NSTATES) return;
    const int write_imag = ((long long)out_size >= 2LL * NSTATES) ? 1 : 0;

    const float* params = (const float*)d_in[pi];
    const float* sre    = (const float*)d_in[si0];
    const float* sim    = (const float*)d_in[si1];
    float*       out    = (float*)d_out;

    const dim3 grid(1024), block(256);

    // L0: LOW (qubits 0..11) then HIGH (12..21).
    vqc_fused<false, false, true,  false><<<grid, block>>>(sre, sim, nullptr, 0, 0, 1, params, 0);
    vqc_fused<true,  false, false, false><<<grid, block>>>(nullptr, nullptr, nullptr, 0, 1, 2, params, 12);
    // L1: LOW with gathered CNOT-chain perm, then HIGH.
    vqc_fused<false, true,  false, false><<<grid, block>>>(nullptr, nullptr, nullptr, 0, 2, 1, params, 22);
    vqc_fused<true,  false, false, false><<<grid, block>>>(nullptr, nullptr, nullptr, 0, 1, 2, params, 34);
    // L2 (stages commute): HIGH with gathered perm, then LOW storing real parts.
    vqc_fused<true,  true,  false, false><<<grid, block>>>(nullptr, nullptr, nullptr, 0, 2, 1, params, 56);
    vqc_fused<false, false, false, true ><<<grid, block>>>(nullptr, nullptr, out, write_imag, 1, 0, params, 44);
}